// round 5
// baseline (speedup 1.0000x reference)
#include <cuda_runtime.h>

// Causal FIR: y[r][t] = sum_{k=0}^{15} b[k] * x[r][t-k], zero initial state per row.
// x: [64, 480000] f32, b: [16] f32, y: [64, 480000] f32.
//
// Each thread produces 8 contiguous outputs of one row:
//   - 6 aligned LDG.128 (24 floats: x[t0-16 .. t0+7]) into registers
//   - 4 LDG.128 for the taps (warp-uniform address -> L1 broadcast)
//   - 128 FFMA over 8 independent accumulator chains (ILP=8)
//   - 2 STG.128
// Per-warp memory-instruction count (~12) keeps LSU and L1tex wavefronts
// under the DRAM (~31us) and FMA (~29us) roofline corner this kernel sits on.
// Grid is 2D: blockIdx.y = batch row (kills the integer division on the
// index path); 480000/8 = 60000 thread-columns per row.

#define T_LEN   480000
#define NTAPS   16
#define BATCH   64
#define OPT     8                    // outputs per thread
#define T_OPT   (T_LEN / OPT)        // 60000 threads per row
#define BLOCK   256

__global__ __launch_bounds__(BLOCK, 4)
void fir_apply_kernel(const float* __restrict__ x,
                      const float* __restrict__ b,
                      float* __restrict__ y)
{
    const int i = blockIdx.x * BLOCK + threadIdx.x;   // thread-column within row
    if (i >= T_OPT) return;
    const int row = blockIdx.y;
    const int t0 = i * OPT;

    const float* __restrict__ xr = x + (size_t)row * T_LEN;
    float* __restrict__ yr = y + (size_t)row * T_LEN;

    // ---- taps: 4x LDG.128 at a warp-uniform address (L1 broadcast) ----
    float bb[NTAPS];
    {
        const float4* b4 = reinterpret_cast<const float4*>(b);
        float4 q0 = __ldg(b4 + 0), q1 = __ldg(b4 + 1),
               q2 = __ldg(b4 + 2), q3 = __ldg(b4 + 3);
        bb[0]  = q0.x; bb[1]  = q0.y; bb[2]  = q0.z; bb[3]  = q0.w;
        bb[4]  = q1.x; bb[5]  = q1.y; bb[6]  = q1.z; bb[7]  = q1.w;
        bb[8]  = q2.x; bb[9]  = q2.y; bb[10] = q2.z; bb[11] = q2.w;
        bb[12] = q3.x; bb[13] = q3.y; bb[14] = q3.z; bb[15] = q3.w;
    }

    // ---- window: xv[m] = x[row][t0 - 16 + m], m = 0..23 ----
    float xv[OPT + NTAPS];   // 24 floats
    if (t0 >= NTAPS) {
        // fast path: all 6 float4 blocks in-bounds; base (t0-16) is 16B-aligned
        const float4* xp = reinterpret_cast<const float4*>(xr + t0 - NTAPS);
        #pragma unroll
        for (int m = 0; m < 6; m++) {
            float4 v = __ldg(xp + m);
            xv[4*m + 0] = v.x; xv[4*m + 1] = v.y;
            xv[4*m + 2] = v.z; xv[4*m + 3] = v.w;
        }
    } else {
        // slow path: only the first 2 thread-columns of each row (128 threads)
        #pragma unroll
        for (int m = 0; m < OPT + NTAPS; m++) {
            const int t = t0 - NTAPS + m;
            xv[m] = (t >= 0) ? xr[t] : 0.0f;
        }
    }

    // ---- 8 independent FMA chains: y[t0+j] = sum_k bb[k] * xv[16 + j - k] ----
    float acc[OPT];
    #pragma unroll
    for (int j = 0; j < OPT; j++) {
        float s = 0.0f;
        #pragma unroll
        for (int k = 0; k < NTAPS; k++) {
            s = fmaf(bb[k], xv[NTAPS + j - k], s);
        }
        acc[j] = s;
    }

    // ---- store 2x STG.128 ----
    float4* yp = reinterpret_cast<float4*>(yr + t0);
    yp[0] = make_float4(acc[0], acc[1], acc[2], acc[3]);
    yp[1] = make_float4(acc[4], acc[5], acc[6], acc[7]);
}

extern "C" void kernel_launch(void* const* d_in, const int* in_sizes, int n_in,
                              void* d_out, int out_size)
{
    const float* x = (const float*)d_in[0];   // [64, 480000] f32
    const float* b = (const float*)d_in[1];   // [16] f32
    float* y = (float*)d_out;                 // [64, 480000] f32

    dim3 grid((T_OPT + BLOCK - 1) / BLOCK, BATCH, 1);   // (235, 64)
    fir_apply_kernel<<<grid, BLOCK>>>(x, b, y);
}

// round 6
// speedup vs baseline: 1.0830x; 1.0830x over previous
#include <cuda_runtime.h>

// Causal FIR: y[r][t] = sum_{k=0}^{15} b[k] * x[r][t-k], zero init per row.
// x: [64, 480000] f32, b: [16] f32, y: [64, 480000] f32.
//
// R3 ncu: L1 = 81.4% (binding), DRAM = 55.6%, fma = 28.6%. Root cause: the
// thread-blocked layout (lane stride 32B) made every LDG/STG span 2x the
// cache lines it needed (~9 wavefronts vs 4).
//
// This version is lane-interleaved: lane L owns 4 contiguous outputs at
// base + 4L, so every LDG.128/STG.128 is a contiguous 512B warp access
// (4 wavefronts, full sector utilization). The 16-float causal halo comes
// from 5 overlapping coalesced loads at offsets -16..0; the shifted ones
// are L1 hits (no extra DRAM traffic). Each warp handles a 256-float tile
// as two 128-float sub-panels (8 outputs/thread) to amortize taps/indexing.
// L1 budget: 52 wf / 256 outputs = 0.20/out -> ~23us, under the ~28-31us
// DRAM floor, which becomes the binder.

#define T_LEN    480000
#define NTAPS    16
#define BATCH    64
#define TILE     256                      // outputs per warp tile
#define N_TILES  (T_LEN / TILE)           // 1875 tiles per row
#define WARPS_PB 8
#define BLOCK    (WARPS_PB * 32)          // 256 threads

__global__ __launch_bounds__(BLOCK, 4)
void fir_apply_kernel(const float* __restrict__ x,
                      const float* __restrict__ b,
                      float* __restrict__ y)
{
    const int lane = threadIdx.x & 31;
    const int warp = threadIdx.x >> 5;
    const int tile = blockIdx.x * WARPS_PB + warp;
    if (tile >= N_TILES) return;
    const int row = blockIdx.y;

    const float* __restrict__ xr = x + (size_t)row * T_LEN;
    float* __restrict__ yr = y + (size_t)row * T_LEN;

    // ---- taps: 4x LDG.128 at warp-uniform address (1 wavefront each) ----
    float bb[NTAPS];
    {
        const float4* b4 = reinterpret_cast<const float4*>(b);
        float4 q0 = __ldg(b4 + 0), q1 = __ldg(b4 + 1),
               q2 = __ldg(b4 + 2), q3 = __ldg(b4 + 3);
        bb[0]  = q0.x; bb[1]  = q0.y; bb[2]  = q0.z; bb[3]  = q0.w;
        bb[4]  = q1.x; bb[5]  = q1.y; bb[6]  = q1.z; bb[7]  = q1.w;
        bb[8]  = q2.x; bb[9]  = q2.y; bb[10] = q2.z; bb[11] = q2.w;
        bb[12] = q3.x; bb[13] = q3.y; bb[14] = q3.z; bb[15] = q3.w;
    }

    const int base = tile * TILE;

    #pragma unroll
    for (int j = 0; j < 2; j++) {
        // lane L computes outputs [t0, t0+4); warp covers 128 contiguous floats
        const int t0 = base + j * 128 + 4 * lane;

        // window w[m] = x[row][t0 - 16 + m], m = 1..19 used
        float w[20];
        if (t0 >= NTAPS) {
            // 5 overlapping, fully coalesced LDG.128 (shifted ones hit L1)
            const float4* p = reinterpret_cast<const float4*>(xr + t0 - NTAPS);
            #pragma unroll
            for (int m = 0; m < 5; m++) {
                float4 v = __ldg(p + m);
                w[4*m + 0] = v.x; w[4*m + 1] = v.y;
                w[4*m + 2] = v.z; w[4*m + 3] = v.w;
            }
        } else {
            // only tile 0, sub-panel 0, lanes 0..3 (4 threads per row)
            #pragma unroll
            for (int m = 0; m < 20; m++) {
                const int t = t0 - NTAPS + m;
                w[m] = (t >= 0) ? xr[t] : 0.0f;
            }
        }

        // 4 independent FMA chains: y[t0+jj] = sum_k bb[k] * w[16 + jj - k]
        float a0 = 0.f, a1 = 0.f, a2 = 0.f, a3 = 0.f;
        #pragma unroll
        for (int k = 0; k < NTAPS; k++) {
            a0 = fmaf(bb[k], w[16 - k], a0);
            a1 = fmaf(bb[k], w[17 - k], a1);
            a2 = fmaf(bb[k], w[18 - k], a2);
            a3 = fmaf(bb[k], w[19 - k], a3);
        }

        // coalesced STG.128 (contiguous 512B per warp)
        *reinterpret_cast<float4*>(yr + t0) = make_float4(a0, a1, a2, a3);
    }
}

extern "C" void kernel_launch(void* const* d_in, const int* in_sizes, int n_in,
                              void* d_out, int out_size)
{
    const float* x = (const float*)d_in[0];   // [64, 480000] f32
    const float* b = (const float*)d_in[1];   // [16] f32
    float* y = (float*)d_out;                 // [64, 480000] f32

    dim3 grid((N_TILES + WARPS_PB - 1) / WARPS_PB, BATCH, 1);   // (235, 64)
    fir_apply_kernel<<<grid, BLOCK>>>(x, b, y);
}